// round 14
// baseline (speedup 1.0000x reference)
#include <cuda_runtime.h>
#include <cuda_fp16.h>
#include <cstdint>

static constexpr int NU = 500000;
static constexpr int NI = 100000;
static constexpr int F  = 300;
static constexpr int D  = 64;
static constexpr int E  = 2000000;
static constexpr int EL = 1000000;

static constexpr int TILES_I = (NI + 127) / 128;   // 782
static constexpr int TILES_U = (NU + 127) / 128;   // 3907
static constexpr int EBLK    = (E + 255) / 256;    // 7813
static constexpr int NB_I    = (NI + 2047) / 2048; // 49
static constexpr int NB_U    = (NU + 2047) / 2048; // 245

// ---------------- device scratch (all features fp32) ----------------
__device__ float g_xi  [NI * 64];
__device__ float g_xiT [NI * 64];   // xi @ Wl1_iu
__device__ float g_xiT2[NI * 64];   // hi @ Wl2_iu
__device__ float g_hi  [NI * 64];
__device__ float g_hi2 [NI * 64];
__device__ float g_hu  [NU * 64];
__device__ float g_hu2 [NU * 64];
__device__ int   g_degI[NI];
__device__ int   g_degU[NU];
__device__ int   g_offI[NI + 1];
__device__ int   g_offU[NU + 1];
__device__ int   g_curI[NI];
__device__ int   g_curU[NU];
__device__ int   g_csrI[E];
__device__ int   g_csrU[E];
__device__ volatile int g_sflag[2][256];
__device__ volatile int g_spart[2][256];
__device__ volatile int g_spref[2][256];
__device__ int   g_scan_cnt;

// ---------------- helpers ----------------
__device__ __forceinline__ uint4 pack8(const float* y) {
    uint4 v;
    *reinterpret_cast<__half2*>(&v.x) = __floats2half2_rn(y[0], y[1]);
    *reinterpret_cast<__half2*>(&v.y) = __floats2half2_rn(y[2], y[3]);
    *reinterpret_cast<__half2*>(&v.z) = __floats2half2_rn(y[4], y[5]);
    *reinterpret_cast<__half2*>(&v.w) = __floats2half2_rn(y[6], y[7]);
    return v;
}

__device__ __forceinline__ void ldsm4(unsigned* r, unsigned a) {
    asm volatile("ldmatrix.sync.aligned.m8n8.x4.shared.b16 {%0,%1,%2,%3}, [%4];"
                 : "=r"(r[0]), "=r"(r[1]), "=r"(r[2]), "=r"(r[3]) : "r"(a));
}
__device__ __forceinline__ void ldsm4t(unsigned* r, unsigned a) {
    asm volatile("ldmatrix.sync.aligned.m8n8.x4.trans.shared.b16 {%0,%1,%2,%3}, [%4];"
                 : "=r"(r[0]), "=r"(r[1]), "=r"(r[2]), "=r"(r[3]) : "r"(a));
}
__device__ __forceinline__ void mma16816(float* c, const unsigned* a,
                                         unsigned b0, unsigned b1) {
    asm volatile("mma.sync.aligned.m16n8k16.row.col.f32.f16.f16.f32 "
                 "{%0,%1,%2,%3}, {%4,%5,%6,%7}, {%8,%9}, {%0,%1,%2,%3};"
                 : "+f"(c[0]), "+f"(c[1]), "+f"(c[2]), "+f"(c[3])
                 : "r"(a[0]), "r"(a[1]), "r"(a[2]), "r"(a[3]), "r"(b0), "r"(b1));
}

// C[8][4] += Xh[128x64] @ Wh[64x64]
__device__ __forceinline__ void mma_pass(float (*C)[4], const __half* Xh,
                                         const __half* Wh, int tid) {
    const int lane = tid & 31, wid = tid >> 5;
    const int lm = lane >> 3, lr8 = lane & 7, lmHi = lm >> 1;
    const int rA = wid * 16 + ((lm & 1) << 3) + lr8;
    const int rA7 = rA & 7;
    const int kBoff = ((lm & 1) << 3) + lr8;
    const unsigned xb = (unsigned)__cvta_generic_to_shared(Xh);
    const unsigned wb = (unsigned)__cvta_generic_to_shared(Wh);
    #pragma unroll
    for (int ks = 0; ks < 4; ks++) {
        unsigned a[4];
        int kc = ks * 2 + lmHi;
        ldsm4(a, xb + (unsigned)(((rA << 6) + ((kc ^ rA7) << 3)) * 2));
        int kB = ks * 16 + kBoff;
        int kB7 = kB & 7;
        #pragma unroll
        for (int g = 0; g < 4; g++) {
            unsigned b[4];
            int nc = g * 2 + lmHi;
            ldsm4t(b, wb + (unsigned)(((kB << 6) + ((nc ^ kB7) << 3)) * 2));
            mma16816(C[2 * g],     a, b[0], b[1]);
            mma16816(C[2 * g + 1], a, b[2], b[3]);
        }
    }
}

// W[64x64] fp32 -> Wh swizzled fp16
__device__ __forceinline__ void load_w(const float* W, __half* Wh, int tid) {
    uint4* WU = reinterpret_cast<uint4*>(Wh);
    #pragma unroll
    for (int j = 0; j < 2; j++) {
        int idx = tid + j * 256;
        int k = idx >> 3, c = idx & 7;
        const float4* p = reinterpret_cast<const float4*>(W + k * 64 + c * 8);
        float4 v0 = p[0], v1 = p[1];
        float y[8] = { v0.x, v0.y, v0.z, v0.w, v1.x, v1.y, v1.z, v1.w };
        WU[(k << 3) + (c ^ (k & 7))] = pack8(y);
    }
}
// fp32 global rows -> Xh swizzled fp16
__device__ __forceinline__ void load_xf(const float* src, __half* Xh, int tile,
                                        int N, int tid) {
    uint4* XU = reinterpret_cast<uint4*>(Xh);
    #pragma unroll
    for (int j = 0; j < 4; j++) {
        int idx = tid + j * 256;
        int r = idx >> 3, c = idx & 7;
        int rg = tile + r;
        float y[8] = { 0.f, 0.f, 0.f, 0.f, 0.f, 0.f, 0.f, 0.f };
        if (rg < N) {
            const float4* p = reinterpret_cast<const float4*>(src + rg * 64 + c * 8);
            float4 v0 = p[0], v1 = p[1];
            y[0] = v0.x; y[1] = v0.y; y[2] = v0.z; y[3] = v0.w;
            y[4] = v1.x; y[5] = v1.y; y[6] = v1.z; y[7] = v1.w;
        }
        XU[(r << 3) + (c ^ (r & 7))] = pack8(y);
    }
}

// epilogue: C frags -> Cs (two halves) -> fn(i, r, y[8]) in (ty,tx) mapping
template <typename Fn>
__device__ __forceinline__ void epilogue(float (*C)[4], float* Cs, int tid, Fn fn) {
    const int lane = tid & 31, wid = tid >> 5;
    const int tx = tid & 7, ty = tid >> 3;
    #pragma unroll
    for (int h = 0; h < 2; h++) {
        __syncthreads();
        if ((wid >> 2) == h) {
            int lr = ((wid & 3) << 4) + (lane >> 2);
            int col = (lane & 3) * 2;
            #pragma unroll
            for (int f = 0; f < 8; f++) {
                *reinterpret_cast<float2*>(&Cs[lr * 68 + f * 8 + col]) =
                    make_float2(C[f][0], C[f][1]);
                *reinterpret_cast<float2*>(&Cs[(lr + 8) * 68 + f * 8 + col]) =
                    make_float2(C[f][2], C[f][3]);
            }
        }
        __syncthreads();
        #pragma unroll
        for (int ii = 0; ii < 2; ii++) {
            int i = 2 * h + ii;
            int r = ty + 32 * i;
            int lr = r - 64 * h;
            float4 v0 = *reinterpret_cast<const float4*>(&Cs[lr * 68 + tx * 8]);
            float4 v1 = *reinterpret_cast<const float4*>(&Cs[lr * 68 + tx * 8 + 4]);
            float y[8] = { v0.x, v0.y, v0.z, v0.w, v1.x, v1.y, v1.z, v1.w };
            fn(i, r, y);
        }
    }
    __syncthreads();
}

// ---------------- 4-edge unrolled fp32 gather-mean ----------------
__device__ __forceinline__ void gather_mean(
    const float* __restrict__ feat, const int* __restrict__ csr,
    int p0, int p1, int tx, float* a)
{
    float s[8];
    #pragma unroll
    for (int t = 0; t < 8; t++) s[t] = 0.f;
    int p = p0;
    for (; p + 4 <= p1; p += 4) {
        int i0 = csr[p], i1 = csr[p + 1], i2 = csr[p + 2], i3 = csr[p + 3];
        const float4* f0 = reinterpret_cast<const float4*>(feat + i0 * 64 + tx * 8);
        const float4* f1 = reinterpret_cast<const float4*>(feat + i1 * 64 + tx * 8);
        const float4* f2 = reinterpret_cast<const float4*>(feat + i2 * 64 + tx * 8);
        const float4* f3 = reinterpret_cast<const float4*>(feat + i3 * 64 + tx * 8);
        float4 a0 = f0[0], a1 = f0[1], b0 = f1[0], b1 = f1[1];
        float4 c0 = f2[0], c1 = f2[1], d0 = f3[0], d1 = f3[1];
        s[0] += (a0.x + b0.x) + (c0.x + d0.x);
        s[1] += (a0.y + b0.y) + (c0.y + d0.y);
        s[2] += (a0.z + b0.z) + (c0.z + d0.z);
        s[3] += (a0.w + b0.w) + (c0.w + d0.w);
        s[4] += (a1.x + b1.x) + (c1.x + d1.x);
        s[5] += (a1.y + b1.y) + (c1.y + d1.y);
        s[6] += (a1.z + b1.z) + (c1.z + d1.z);
        s[7] += (a1.w + b1.w) + (c1.w + d1.w);
    }
    for (; p < p1; p++) {
        const float4* f0 = reinterpret_cast<const float4*>(feat + csr[p] * 64 + tx * 8);
        float4 a0 = f0[0], a1 = f0[1];
        s[0] += a0.x; s[1] += a0.y; s[2] += a0.z; s[3] += a0.w;
        s[4] += a1.x; s[5] += a1.y; s[6] += a1.z; s[7] += a1.w;
    }
    float rc = 1.f / fmaxf((float)(p1 - p0), 1.f);
    #pragma unroll
    for (int t = 0; t < 8; t++) a[t] += rc * s[t];
}

// ---------------- zero ----------------
__global__ void k_zero_deg() {
    int i = blockIdx.x * blockDim.x + threadIdx.x;
    if (i < NU) { g_degU[i] = 0; g_curU[i] = 0; }
    if (i < NI) { g_degI[i] = 0; g_curI[i] = 0; }
    if (i < 256) { g_sflag[0][i] = 0; g_sflag[1][i] = 0; }
    if (i == 0) g_scan_cnt = 0;
}

// ---------------- fused scan (decoupled lookback) + CSR fill ----------------
__global__ void k_scanfill(const int* __restrict__ es, const int* __restrict__ ed) {
    const int t = threadIdx.x;
    if (blockIdx.x >= NB_I + NB_U) {
        // ---- fill branch: wait for all scan blocks, then fill CSR ----
        if (t == 0) {
            volatile int* cnt = &g_scan_cnt;
            while (*cnt < NB_I + NB_U) { }
        }
        __syncthreads();
        int e = (int)(blockIdx.x - NB_I - NB_U) * 256 + t;
        if (e < E) {
            int u = es[e], it = ed[e];
            g_csrI[g_offI[it] + atomicAdd(&g_curI[it], 1)] = u;
            g_csrU[g_offU[u] + atomicAdd(&g_curU[u], 1)] = it;
        }
        return;
    }

    int dom, blk, n;
    const int* deg; int* out;
    if (blockIdx.x < NB_I) { dom = 0; blk = blockIdx.x;        deg = g_degI; out = g_offI; n = NI; }
    else                   { dom = 1; blk = blockIdx.x - NB_I; deg = g_degU; out = g_offU; n = NU; }

    __shared__ int ws[8];
    __shared__ int s_tot;
    __shared__ int s_exc;
    const int base = blk * 2048 + t * 8;
    int v[8];
    #pragma unroll
    for (int j = 0; j < 8; j++) v[j] = (base + j < n) ? deg[base + j] : 0;
    int s = 0;
    #pragma unroll
    for (int j = 0; j < 8; j++) { int x = v[j]; v[j] = s; s += x; }
    const int lane = t & 31, wid = t >> 5;
    int sx = s;
    #pragma unroll
    for (int o = 1; o < 32; o <<= 1) {
        int y = __shfl_up_sync(0xffffffffu, sx, o);
        if (lane >= o) sx += y;
    }
    if (lane == 31) ws[wid] = sx;
    __syncthreads();
    if (wid == 0 && lane < 8) {
        int b = ws[lane];
        int bx = b;
        #pragma unroll
        for (int o = 1; o < 8; o <<= 1) {
            int y = __shfl_up_sync(0xffu, bx, o);
            if (lane >= o) bx += y;
        }
        ws[lane] = bx - b;
        if (lane == 7) s_tot = bx;
    }
    __syncthreads();
    const int loff = ws[wid] + (sx - s);

    if (t == 0) {
        int tot = s_tot;
        g_spart[dom][blk] = tot;
        __threadfence();
        if (blk == 0) {
            g_spref[dom][0] = tot;
            __threadfence();
            g_sflag[dom][0] = 2;
            s_exc = 0;
        } else {
            g_sflag[dom][blk] = 1;
            int exc = 0;
            int pb = blk - 1;
            while (pb >= 0) {
                int f;
                while ((f = g_sflag[dom][pb]) == 0) { }
                if (f == 2) { exc += g_spref[dom][pb]; break; }
                exc += g_spart[dom][pb];
                pb--;
            }
            g_spref[dom][blk] = exc + tot;
            __threadfence();
            g_sflag[dom][blk] = 2;
            s_exc = exc;
        }
    }
    __syncthreads();
    const int exc = s_exc;
    #pragma unroll
    for (int j = 0; j < 8; j++)
        if (base + j < n) out[base + j] = exc + loff + v[j];
    if (blockIdx.x == 0 && t == 0) { g_offI[NI] = E; g_offU[NU] = E; }

    // signal completion
    __syncthreads();
    if (t == 0) {
        __threadfence();
        atomicAdd(&g_scan_cnt, 1);
    }
}

// ============================================================================
// fused: [item linear (MMA) + xiT1 tail, fp32 outputs] || degree count
// ============================================================================
__global__ __launch_bounds__(256) void k_lin_count(
    const float* __restrict__ X, const float* __restrict__ W,
    const float* __restrict__ bias, const float* __restrict__ Wl,
    const int* __restrict__ es, const int* __restrict__ ed)
{
    if (blockIdx.x >= TILES_I) {
        int i = (int)(blockIdx.x - TILES_I) * 256 + threadIdx.x;
        if (i < E) {
            atomicAdd(&g_degU[es[i]], 1);
            atomicAdd(&g_degI[ed[i]], 1);
        }
        return;
    }

    __shared__ __align__(16) __half Xh[128 * 64];
    __shared__ __align__(16) __half Wh[64 * 64];
    __shared__ float Cs[64 * 68];
    const int tid = threadIdx.x;
    const int tx = tid & 7, ty = tid >> 3;
    const int tile = blockIdx.x * 128;
    uint4* XU = reinterpret_cast<uint4*>(Xh);
    uint4* WU = reinterpret_cast<uint4*>(Wh);

    float C[8][4];
    #pragma unroll
    for (int f = 0; f < 8; f++)
        #pragma unroll
        for (int q = 0; q < 4; q++) C[f][q] = 0.f;

    #pragma unroll 1
    for (int kc = 0; kc < 5; kc++) {
        const int k0 = kc * 64;
        const int kn = (k0 + 64 <= F) ? 64 : (F - k0);   // 64,...,44
        __syncthreads();
        #pragma unroll
        for (int j = 0; j < 2; j++) {
            int idx = tid + j * 256;
            int k = idx >> 3, c = idx & 7;
            float y[8] = { 0.f, 0.f, 0.f, 0.f, 0.f, 0.f, 0.f, 0.f };
            if (k < kn) {
                const float4* p = reinterpret_cast<const float4*>(W + (k0 + k) * 64 + c * 8);
                float4 v0 = p[0], v1 = p[1];
                y[0] = v0.x; y[1] = v0.y; y[2] = v0.z; y[3] = v0.w;
                y[4] = v1.x; y[5] = v1.y; y[6] = v1.z; y[7] = v1.w;
            }
            WU[(k << 3) + (c ^ (k & 7))] = pack8(y);
        }
        #pragma unroll
        for (int j = 0; j < 4; j++) {
            int idx = tid + j * 256;
            int r = idx >> 3, c = idx & 7;
            int rg = tile + r;
            float y[8] = { 0.f, 0.f, 0.f, 0.f, 0.f, 0.f, 0.f, 0.f };
            if (rg < NI) {
                const float* xp = X + rg * F + k0 + c * 8;
                if (c * 8 + 3 < kn) {
                    float4 v = *reinterpret_cast<const float4*>(xp);
                    y[0] = v.x; y[1] = v.y; y[2] = v.z; y[3] = v.w;
                }
                if (c * 8 + 7 < kn) {
                    float4 v = *reinterpret_cast<const float4*>(xp + 4);
                    y[4] = v.x; y[5] = v.y; y[6] = v.z; y[7] = v.w;
                }
            }
            XU[(r << 3) + (c ^ (r & 7))] = pack8(y);
        }
        __syncthreads();
        mma_pass(C, Xh, Wh, tid);
    }

    float yv[4][8];
    epilogue(C, Cs, tid, [&](int i, int r, float* y) {
        int rg = tile + r;
        #pragma unroll
        for (int t = 0; t < 8; t++) y[t] += bias[tx * 8 + t];
        if (rg < NI) {
            float4* yp = reinterpret_cast<float4*>(g_xi + rg * 64 + tx * 8);
            yp[0] = make_float4(y[0], y[1], y[2], y[3]);
            yp[1] = make_float4(y[4], y[5], y[6], y[7]);
        }
        #pragma unroll
        for (int t = 0; t < 8; t++) yv[i][t] = y[t];
    });

    // tail: xiT1 = xi_tile @ Wl1_iu (fp32 out)
    #pragma unroll
    for (int i = 0; i < 4; i++) {
        int r = ty + 32 * i;
        XU[(r << 3) + (tx ^ (r & 7))] = pack8(yv[i]);
    }
    load_w(Wl, Wh, tid);
    __syncthreads();
    float C2[8][4];
    #pragma unroll
    for (int f = 0; f < 8; f++)
        #pragma unroll
        for (int q = 0; q < 4; q++) C2[f][q] = 0.f;
    mma_pass(C2, Xh, Wh, tid);
    epilogue(C2, Cs, tid, [&](int i, int r, float* y) {
        int rg = tile + r;
        if (rg < NI) {
            float4* yp = reinterpret_cast<float4*>(g_xiT + rg * 64 + tx * 8);
            yp[0] = make_float4(y[0], y[1], y[2], y[3]);
            yp[1] = make_float4(y[4], y[5], y[6], y[7]);
        }
    });
}

// ============================================================================
// fused node update (fp32 features, fp16 MMA operands)
// ============================================================================
__device__ __forceinline__ void item_tile(
    int tile, const float* __restrict__ srcF, const float* __restrict__ Wl,
    const float* __restrict__ Xsrc, const float* __restrict__ Wr,
    const float* __restrict__ bias, int relu, float* __restrict__ Yf,
    const float* __restrict__ WlNext, float* __restrict__ xiTout,
    __half* Xh, __half* Wh, float* Cs)
{
    const int tid = threadIdx.x;
    const int tx = tid & 7, ty = tid >> 3;
    uint4* XU = reinterpret_cast<uint4*>(Xh);

    // gather-mean (fp32 src) -> Xh fp16
    #pragma unroll 1
    for (int i = 0; i < 4; i++) {
        int r = ty + 32 * i, rg = tile + r;
        float a[8] = { 0.f, 0.f, 0.f, 0.f, 0.f, 0.f, 0.f, 0.f };
        if (rg < NI) gather_mean(srcF, g_csrI, g_offI[rg], g_offI[rg + 1], tx, a);
        XU[(r << 3) + (tx ^ (r & 7))] = pack8(a);
    }
    load_w(Wl, Wh, tid);
    __syncthreads();

    float C[8][4];
    #pragma unroll
    for (int f = 0; f < 8; f++)
        #pragma unroll
        for (int q = 0; q < 4; q++) C[f][q] = 0.f;
    mma_pass(C, Xh, Wh, tid);
    __syncthreads();

    load_xf(Xsrc, Xh, tile, NI, tid);
    load_w(Wr, Wh, tid);
    __syncthreads();
    mma_pass(C, Xh, Wh, tid);

    float yv[4][8];
    epilogue(C, Cs, tid, [&](int i, int r, float* y) {
        int rg = tile + r;
        #pragma unroll
        for (int t = 0; t < 8; t++) {
            y[t] += bias[tx * 8 + t];
            if (relu) y[t] = fmaxf(y[t], 0.f);
        }
        if (rg < NI) {
            float4* yp = reinterpret_cast<float4*>(Yf + rg * 64 + tx * 8);
            yp[0] = make_float4(y[0], y[1], y[2], y[3]);
            yp[1] = make_float4(y[4], y[5], y[6], y[7]);
        }
        if (WlNext) {
            #pragma unroll
            for (int t = 0; t < 8; t++) yv[i][t] = y[t];
        }
    });

    if (WlNext) {
        #pragma unroll
        for (int i = 0; i < 4; i++) {
            int r = ty + 32 * i;
            XU[(r << 3) + (tx ^ (r & 7))] = pack8(yv[i]);
        }
        load_w(WlNext, Wh, tid);
        __syncthreads();
        float C2[8][4];
        #pragma unroll
        for (int f = 0; f < 8; f++)
            #pragma unroll
            for (int q = 0; q < 4; q++) C2[f][q] = 0.f;
        mma_pass(C2, Xh, Wh, tid);
        epilogue(C2, Cs, tid, [&](int i, int r, float* y) {
            int rg = tile + r;
            if (rg < NI) {
                float4* yp = reinterpret_cast<float4*>(xiTout + rg * 64 + tx * 8);
                yp[0] = make_float4(y[0], y[1], y[2], y[3]);
                yp[1] = make_float4(y[4], y[5], y[6], y[7]);
            }
        });
    }
}

__device__ __forceinline__ void user_tile(
    int tile, const float* __restrict__ gsrcF, const float* __restrict__ Xsrc,
    const float* __restrict__ Wr, const float* __restrict__ bias, int relu,
    float* __restrict__ Yf, __half* Xh, __half* Wh, float* Cs)
{
    const int tid = threadIdx.x;
    const int tx = tid & 7, ty = tid >> 3;

    load_xf(Xsrc, Xh, tile, NU, tid);
    load_w(Wr, Wh, tid);
    __syncthreads();

    float C[8][4];
    #pragma unroll
    for (int f = 0; f < 8; f++)
        #pragma unroll
        for (int q = 0; q < 4; q++) C[f][q] = 0.f;
    mma_pass(C, Xh, Wh, tid);

    float a[4][8];
    #pragma unroll 1
    for (int i = 0; i < 4; i++) {
        #pragma unroll
        for (int t = 0; t < 8; t++) a[i][t] = 0.f;
        int rg = tile + ty + 32 * i;
        if (rg < NU) gather_mean(gsrcF, g_csrU, g_offU[rg], g_offU[rg + 1], tx, a[i]);
    }

    epilogue(C, Cs, tid, [&](int i, int r, float* y) {
        int rg = tile + r;
        #pragma unroll
        for (int t = 0; t < 8; t++) {
            y[t] += bias[tx * 8 + t] + a[i][t];
            if (relu) y[t] = fmaxf(y[t], 0.f);
        }
        if (rg < NU) {
            float4* yp = reinterpret_cast<float4*>(Yf + rg * 64 + tx * 8);
            yp[0] = make_float4(y[0], y[1], y[2], y[3]);
            yp[1] = make_float4(y[4], y[5], y[6], y[7]);
        }
    });
}

__global__ __launch_bounds__(256) void k_upd(
    const float* __restrict__ itemGsrc, const float* __restrict__ Wl_ui,
    const float* __restrict__ itemXsrc, const float* __restrict__ Wr_ui,
    const float* __restrict__ b_ui, float* __restrict__ Yi,
    const float* __restrict__ userGsrc, const float* __restrict__ userXsrc,
    const float* __restrict__ Wr_iu, const float* __restrict__ b_iu,
    float* __restrict__ Yu,
    const float* __restrict__ WlNext, float* __restrict__ xiTout,
    int relu)
{
    __shared__ __align__(16) __half Xh[128 * 64];
    __shared__ __align__(16) __half Wh[64 * 64];
    __shared__ float Cs[64 * 68];
    if (blockIdx.x < TILES_I) {
        item_tile(blockIdx.x * 128, itemGsrc, Wl_ui, itemXsrc, Wr_ui, b_ui, relu,
                  Yi, WlNext, xiTout, Xh, Wh, Cs);
    } else {
        user_tile((int)(blockIdx.x - TILES_I) * 128, userGsrc, userXsrc,
                  Wr_iu, b_iu, relu, Yu, Xh, Wh, Cs);
    }
}

// ---------------- predictor ----------------
__global__ void k_dot(const float* __restrict__ hu, const float* __restrict__ hi,
                      const int* __restrict__ ls, const int* __restrict__ ld,
                      float* __restrict__ out) {
    int i = blockIdx.x * blockDim.x + threadIdx.x;
    int e = i >> 2;
    int j = i & 3;
    if (e >= EL) return;
    int u = ls[e];
    int v = ld[e];
    const float4* pa = reinterpret_cast<const float4*>(hu + u * 64 + j * 16);
    const float4* pb = reinterpret_cast<const float4*>(hi + v * 64 + j * 16);
    float4 a0 = pa[0], a1 = pa[1], a2 = pa[2], a3 = pa[3];
    float4 b0 = pb[0], b1 = pb[1], b2 = pb[2], b3 = pb[3];
    float s = a0.x * b0.x + a0.y * b0.y + a0.z * b0.z + a0.w * b0.w
            + a1.x * b1.x + a1.y * b1.y + a1.z * b1.z + a1.w * b1.w
            + a2.x * b2.x + a2.y * b2.y + a2.z * b2.z + a2.w * b2.w
            + a3.x * b3.x + a3.y * b3.y + a3.z * b3.z + a3.w * b3.w;
    s += __shfl_down_sync(0xffffffffu, s, 2, 4);
    s += __shfl_down_sync(0xffffffffu, s, 1, 4);
    if (j == 0) out[e] = s;
}

// ---------------- launch ----------------
extern "C" void kernel_launch(void* const* d_in, const int* in_sizes, int n_in,
                              void* d_out, int out_size) {
    const float* user_emb = (const float*)d_in[0];
    const float* item_x   = (const float*)d_in[1];
    const float* Wlin     = (const float*)d_in[2];
    const float* blin     = (const float*)d_in[3];
    const float* Wl1_ui   = (const float*)d_in[4];
    const float* Wr1_ui   = (const float*)d_in[5];
    const float* b1_ui    = (const float*)d_in[6];
    const float* Wl1_iu   = (const float*)d_in[7];
    const float* Wr1_iu   = (const float*)d_in[8];
    const float* b1_iu    = (const float*)d_in[9];
    const float* Wl2_ui   = (const float*)d_in[10];
    const float* Wr2_ui   = (const float*)d_in[11];
    const float* b2_ui    = (const float*)d_in[12];
    const float* Wl2_iu   = (const float*)d_in[13];
    const float* Wr2_iu   = (const float*)d_in[14];
    const float* b2_iu    = (const float*)d_in[15];
    const int* es   = (const int*)d_in[17];
    const int* ed   = (const int*)d_in[18];
    const int* ls   = (const int*)d_in[19];
    const int* ldst = (const int*)d_in[20];
    float* out = (float*)d_out;

    float *xi, *xiT, *xiT2, *hi, *hi2, *hu, *hu2;
    cudaGetSymbolAddress((void**)&xi,   g_xi);
    cudaGetSymbolAddress((void**)&xiT,  g_xiT);
    cudaGetSymbolAddress((void**)&xiT2, g_xiT2);
    cudaGetSymbolAddress((void**)&hi,   g_hi);
    cudaGetSymbolAddress((void**)&hi2,  g_hi2);
    cudaGetSymbolAddress((void**)&hu,   g_hu);
    cudaGetSymbolAddress((void**)&hu2,  g_hu2);

    // 0: zero degrees / cursors / scan state
    k_zero_deg<<<(NU + 255) / 256, 256>>>();
    // 1: fused [item linear (MMA) + fp32 xiT1 tail || degree count]
    k_lin_count<<<TILES_I + EBLK, 256>>>(item_x, Wlin, blin, Wl1_iu, es, ed);
    // 2: fused [exclusive scan || CSR fill (spin on scan completion)]
    k_scanfill<<<NB_I + NB_U + EBLK, 256>>>(es, ed);
    // 3: layer 1 fused [item update (+xiT2 tail) || user update]
    k_upd<<<TILES_I + TILES_U, 256>>>(user_emb, Wl1_ui, xi, Wr1_ui, b1_ui, hi,
                                      xiT, user_emb, Wr1_iu, b1_iu, hu,
                                      Wl2_iu, xiT2, 1);
    // 4: layer 2 fused
    k_upd<<<TILES_I + TILES_U, 256>>>(hu, Wl2_ui, hi, Wr2_ui, b2_ui, hi2,
                                      xiT2, hu, Wr2_iu, b2_iu, hu2,
                                      nullptr, nullptr, 0);
    // 5: predictor
    k_dot<<<(EL * 4 + 255) / 256, 256>>>(hu2, hi2, ls, ldst, out);
}

// round 15
// speedup vs baseline: 1.3446x; 1.3446x over previous
#include <cuda_runtime.h>
#include <cuda_fp16.h>
#include <cstdint>

static constexpr int NU = 500000;
static constexpr int NI = 100000;
static constexpr int F  = 300;
static constexpr int D  = 64;
static constexpr int E  = 2000000;
static constexpr int EL = 1000000;

static constexpr int TILES_I = (NI + 127) / 128;   // 782
static constexpr int TILES_U = (NU + 127) / 128;   // 3907
static constexpr int EBLK    = (E + 255) / 256;    // 7813
static constexpr int CONVB   = (NU * 8 + 255) / 256;
static constexpr int NB_I    = (NI + 2047) / 2048; // 49
static constexpr int NB_U    = (NU + 2047) / 2048; // 245

// ---------------- device scratch ----------------
__device__ uint4 g_xih  [NI * 8];   // fp16 xi
__device__ uint4 g_hih  [NI * 8];   // fp16 hi (layer-1 item out)
__device__ uint4 g_uembh[NU * 8];   // fp16 user_emb
__device__ uint4 g_huh  [NU * 8];   // fp16 hu (layer-1 user out)
__device__ uint4 g_xiTh [NI * 8];   // fp16 xi @ Wl1_iu
__device__ uint4 g_xiT2h[NI * 8];   // fp16 hi @ Wl2_iu
__device__ float g_hi2[NI * 64];    // fp32 final item (dot)
__device__ float g_hu2[NU * 64];    // fp32 final user (dot)
__device__ int   g_degI[NI];
__device__ int   g_degU[NU];
__device__ int   g_offI[NI + 1];
__device__ int   g_offU[NU + 1];
__device__ int   g_curI[NI];
__device__ int   g_curU[NU];
__device__ int   g_csrI[E];
__device__ int   g_csrU[E];
__device__ volatile int g_sflag[2][256];
__device__ volatile int g_spart[2][256];
__device__ volatile int g_spref[2][256];
__device__ int   g_scan_cnt;

// ---------------- helpers ----------------
__device__ __forceinline__ uint4 pack8(const float* y) {
    uint4 v;
    *reinterpret_cast<__half2*>(&v.x) = __floats2half2_rn(y[0], y[1]);
    *reinterpret_cast<__half2*>(&v.y) = __floats2half2_rn(y[2], y[3]);
    *reinterpret_cast<__half2*>(&v.z) = __floats2half2_rn(y[4], y[5]);
    *reinterpret_cast<__half2*>(&v.w) = __floats2half2_rn(y[6], y[7]);
    return v;
}
__device__ __forceinline__ void acc8(uint4 v, float* s) {
    float2 f0 = __half22float2(*reinterpret_cast<__half2*>(&v.x));
    float2 f1 = __half22float2(*reinterpret_cast<__half2*>(&v.y));
    float2 f2 = __half22float2(*reinterpret_cast<__half2*>(&v.z));
    float2 f3 = __half22float2(*reinterpret_cast<__half2*>(&v.w));
    s[0] += f0.x; s[1] += f0.y; s[2] += f1.x; s[3] += f1.y;
    s[4] += f2.x; s[5] += f2.y; s[6] += f3.x; s[7] += f3.y;
}

__device__ __forceinline__ void ldsm4(unsigned* r, unsigned a) {
    asm volatile("ldmatrix.sync.aligned.m8n8.x4.shared.b16 {%0,%1,%2,%3}, [%4];"
                 : "=r"(r[0]), "=r"(r[1]), "=r"(r[2]), "=r"(r[3]) : "r"(a));
}
__device__ __forceinline__ void ldsm4t(unsigned* r, unsigned a) {
    asm volatile("ldmatrix.sync.aligned.m8n8.x4.trans.shared.b16 {%0,%1,%2,%3}, [%4];"
                 : "=r"(r[0]), "=r"(r[1]), "=r"(r[2]), "=r"(r[3]) : "r"(a));
}
__device__ __forceinline__ void mma16816(float* c, const unsigned* a,
                                         unsigned b0, unsigned b1) {
    asm volatile("mma.sync.aligned.m16n8k16.row.col.f32.f16.f16.f32 "
                 "{%0,%1,%2,%3}, {%4,%5,%6,%7}, {%8,%9}, {%0,%1,%2,%3};"
                 : "+f"(c[0]), "+f"(c[1]), "+f"(c[2]), "+f"(c[3])
                 : "r"(a[0]), "r"(a[1]), "r"(a[2]), "r"(a[3]), "r"(b0), "r"(b1));
}

// C[8][4] += Xh[128x64] @ Wh[64x64]
__device__ __forceinline__ void mma_pass(float (*C)[4], const __half* Xh,
                                         const __half* Wh, int tid) {
    const int lane = tid & 31, wid = tid >> 5;
    const int lm = lane >> 3, lr8 = lane & 7, lmHi = lm >> 1;
    const int rA = wid * 16 + ((lm & 1) << 3) + lr8;
    const int rA7 = rA & 7;
    const int kBoff = ((lm & 1) << 3) + lr8;
    const unsigned xb = (unsigned)__cvta_generic_to_shared(Xh);
    const unsigned wb = (unsigned)__cvta_generic_to_shared(Wh);
    #pragma unroll
    for (int ks = 0; ks < 4; ks++) {
        unsigned a[4];
        int kc = ks * 2 + lmHi;
        ldsm4(a, xb + (unsigned)(((rA << 6) + ((kc ^ rA7) << 3)) * 2));
        int kB = ks * 16 + kBoff;
        int kB7 = kB & 7;
        #pragma unroll
        for (int g = 0; g < 4; g++) {
            unsigned b[4];
            int nc = g * 2 + lmHi;
            ldsm4t(b, wb + (unsigned)(((kB << 6) + ((nc ^ kB7) << 3)) * 2));
            mma16816(C[2 * g],     a, b[0], b[1]);
            mma16816(C[2 * g + 1], a, b[2], b[3]);
        }
    }
}

// W[64x64] fp32 -> Wh swizzled fp16
__device__ __forceinline__ void load_w(const float* W, __half* Wh, int tid) {
    uint4* WU = reinterpret_cast<uint4*>(Wh);
    #pragma unroll
    for (int j = 0; j < 2; j++) {
        int idx = tid + j * 256;
        int k = idx >> 3, c = idx & 7;
        const float4* p = reinterpret_cast<const float4*>(W + k * 64 + c * 8);
        float4 v0 = p[0], v1 = p[1];
        float y[8] = { v0.x, v0.y, v0.z, v0.w, v1.x, v1.y, v1.z, v1.w };
        WU[(k << 3) + (c ^ (k & 7))] = pack8(y);
    }
}
// fp16 global rows -> Xh swizzled
__device__ __forceinline__ void load_xh(const uint4* src, __half* Xh, int tile,
                                        int N, int tid) {
    uint4* XU = reinterpret_cast<uint4*>(Xh);
    #pragma unroll
    for (int j = 0; j < 4; j++) {
        int idx = tid + j * 256;
        int r = idx >> 3, c = idx & 7;
        int rg = tile + r;
        uint4 v = make_uint4(0u, 0u, 0u, 0u);
        if (rg < N) v = src[(rg << 3) + c];
        XU[(r << 3) + (c ^ (r & 7))] = v;
    }
}

// epilogue: C frags -> Cs (two halves) -> fn(i, r, y[8]) in (ty,tx) mapping
template <typename Fn>
__device__ __forceinline__ void epilogue(float (*C)[4], float* Cs, int tid, Fn fn) {
    const int lane = tid & 31, wid = tid >> 5;
    const int tx = tid & 7, ty = tid >> 3;
    #pragma unroll
    for (int h = 0; h < 2; h++) {
        __syncthreads();
        if ((wid >> 2) == h) {
            int lr = ((wid & 3) << 4) + (lane >> 2);
            int col = (lane & 3) * 2;
            #pragma unroll
            for (int f = 0; f < 8; f++) {
                *reinterpret_cast<float2*>(&Cs[lr * 68 + f * 8 + col]) =
                    make_float2(C[f][0], C[f][1]);
                *reinterpret_cast<float2*>(&Cs[(lr + 8) * 68 + f * 8 + col]) =
                    make_float2(C[f][2], C[f][3]);
            }
        }
        __syncthreads();
        #pragma unroll
        for (int ii = 0; ii < 2; ii++) {
            int i = 2 * h + ii;
            int r = ty + 32 * i;
            int lr = r - 64 * h;
            float4 v0 = *reinterpret_cast<const float4*>(&Cs[lr * 68 + tx * 8]);
            float4 v1 = *reinterpret_cast<const float4*>(&Cs[lr * 68 + tx * 8 + 4]);
            float y[8] = { v0.x, v0.y, v0.z, v0.w, v1.x, v1.y, v1.z, v1.w };
            fn(i, r, y);
        }
    }
    __syncthreads();
}

// ---------------- 4-edge unrolled fp16 gather-mean ----------------
__device__ __forceinline__ void gather_mean_h(
    const uint4* __restrict__ feat, const int* __restrict__ csr,
    int p0, int p1, int tx, float* a)
{
    float s[8];
    #pragma unroll
    for (int t = 0; t < 8; t++) s[t] = 0.f;
    int p = p0;
    for (; p + 4 <= p1; p += 4) {
        int i0 = csr[p], i1 = csr[p + 1], i2 = csr[p + 2], i3 = csr[p + 3];
        uint4 v0 = feat[i0 * 8 + tx];
        uint4 v1 = feat[i1 * 8 + tx];
        uint4 v2 = feat[i2 * 8 + tx];
        uint4 v3 = feat[i3 * 8 + tx];
        acc8(v0, s); acc8(v1, s); acc8(v2, s); acc8(v3, s);
    }
    for (; p < p1; p++) acc8(feat[csr[p] * 8 + tx], s);
    float rc = 1.f / fmaxf((float)(p1 - p0), 1.f);
    #pragma unroll
    for (int t = 0; t < 8; t++) a[t] += rc * s[t];
}

// ---------------- zero ----------------
__global__ void k_zero_deg() {
    int i = blockIdx.x * blockDim.x + threadIdx.x;
    if (i < NU) { g_degU[i] = 0; g_curU[i] = 0; }
    if (i < NI) { g_degI[i] = 0; g_curI[i] = 0; }
    if (i < 256) { g_sflag[0][i] = 0; g_sflag[1][i] = 0; }
    if (i == 0) g_scan_cnt = 0;
}

// ---------------- fused scan (decoupled lookback) + CSR fill ----------------
__global__ void k_scanfill(const int* __restrict__ es, const int* __restrict__ ed) {
    const int t = threadIdx.x;
    if (blockIdx.x >= NB_I + NB_U) {
        if (t == 0) {
            volatile int* cnt = &g_scan_cnt;
            while (*cnt < NB_I + NB_U) { }
        }
        __syncthreads();
        int e = (int)(blockIdx.x - NB_I - NB_U) * 256 + t;
        if (e < E) {
            int u = es[e], it = ed[e];
            g_csrI[g_offI[it] + atomicAdd(&g_curI[it], 1)] = u;
            g_csrU[g_offU[u] + atomicAdd(&g_curU[u], 1)] = it;
        }
        return;
    }

    int dom, blk, n;
    const int* deg; int* out;
    if (blockIdx.x < NB_I) { dom = 0; blk = blockIdx.x;        deg = g_degI; out = g_offI; n = NI; }
    else                   { dom = 1; blk = blockIdx.x - NB_I; deg = g_degU; out = g_offU; n = NU; }

    __shared__ int ws[8];
    __shared__ int s_tot;
    __shared__ int s_exc;
    const int base = blk * 2048 + t * 8;
    int v[8];
    #pragma unroll
    for (int j = 0; j < 8; j++) v[j] = (base + j < n) ? deg[base + j] : 0;
    int s = 0;
    #pragma unroll
    for (int j = 0; j < 8; j++) { int x = v[j]; v[j] = s; s += x; }
    const int lane = t & 31, wid = t >> 5;
    int sx = s;
    #pragma unroll
    for (int o = 1; o < 32; o <<= 1) {
        int y = __shfl_up_sync(0xffffffffu, sx, o);
        if (lane >= o) sx += y;
    }
    if (lane == 31) ws[wid] = sx;
    __syncthreads();
    if (wid == 0 && lane < 8) {
        int b = ws[lane];
        int bx = b;
        #pragma unroll
        for (int o = 1; o < 8; o <<= 1) {
            int y = __shfl_up_sync(0xffu, bx, o);
            if (lane >= o) bx += y;
        }
        ws[lane] = bx - b;
        if (lane == 7) s_tot = bx;
    }
    __syncthreads();
    const int loff = ws[wid] + (sx - s);

    if (t == 0) {
        int tot = s_tot;
        g_spart[dom][blk] = tot;
        __threadfence();
        if (blk == 0) {
            g_spref[dom][0] = tot;
            __threadfence();
            g_sflag[dom][0] = 2;
            s_exc = 0;
        } else {
            g_sflag[dom][blk] = 1;
            int exc = 0;
            int pb = blk - 1;
            while (pb >= 0) {
                int f;
                while ((f = g_sflag[dom][pb]) == 0) { }
                if (f == 2) { exc += g_spref[dom][pb]; break; }
                exc += g_spart[dom][pb];
                pb--;
            }
            g_spref[dom][blk] = exc + tot;
            __threadfence();
            g_sflag[dom][blk] = 2;
            s_exc = exc;
        }
    }
    __syncthreads();
    const int exc = s_exc;
    #pragma unroll
    for (int j = 0; j < 8; j++)
        if (base + j < n) out[base + j] = exc + loff + v[j];
    if (blockIdx.x == 0 && t == 0) { g_offI[NI] = E; g_offU[NU] = E; }

    __syncthreads();
    if (t == 0) {
        __threadfence();
        atomicAdd(&g_scan_cnt, 1);
    }
}

// ============================================================================
// fused: [item linear (MMA) + fp16 xiT1 tail] || degree count || user_emb conv
// ============================================================================
__global__ __launch_bounds__(256, 3) void k_lin_count(
    const float* __restrict__ X, const float* __restrict__ W,
    const float* __restrict__ bias, const float* __restrict__ Wl,
    const float* __restrict__ ue,
    const int* __restrict__ es, const int* __restrict__ ed)
{
    if (blockIdx.x >= TILES_I + EBLK) {
        int i = (int)(blockIdx.x - TILES_I - EBLK) * 256 + threadIdx.x;
        if (i < NU * 8) {
            int row = i >> 3, part = i & 7;
            const float4* p = reinterpret_cast<const float4*>(ue + row * 64 + part * 8);
            float4 v0 = p[0], v1 = p[1];
            float y[8] = { v0.x, v0.y, v0.z, v0.w, v1.x, v1.y, v1.z, v1.w };
            g_uembh[i] = pack8(y);
        }
        return;
    }
    if (blockIdx.x >= TILES_I) {
        int i = (int)(blockIdx.x - TILES_I) * 256 + threadIdx.x;
        if (i < E) {
            atomicAdd(&g_degU[es[i]], 1);
            atomicAdd(&g_degI[ed[i]], 1);
        }
        return;
    }

    __shared__ __align__(16) __half Xh[128 * 64];
    __shared__ __align__(16) __half Wh[64 * 64];
    __shared__ float Cs[64 * 68];
    const int tid = threadIdx.x;
    const int tx = tid & 7, ty = tid >> 3;
    const int tile = blockIdx.x * 128;
    uint4* XU = reinterpret_cast<uint4*>(Xh);
    uint4* WU = reinterpret_cast<uint4*>(Wh);

    float C[8][4];
    #pragma unroll
    for (int f = 0; f < 8; f++)
        #pragma unroll
        for (int q = 0; q < 4; q++) C[f][q] = 0.f;

    #pragma unroll 1
    for (int kc = 0; kc < 5; kc++) {
        const int k0 = kc * 64;
        const int kn = (k0 + 64 <= F) ? 64 : (F - k0);
        __syncthreads();
        #pragma unroll
        for (int j = 0; j < 2; j++) {
            int idx = tid + j * 256;
            int k = idx >> 3, c = idx & 7;
            float y[8] = { 0.f, 0.f, 0.f, 0.f, 0.f, 0.f, 0.f, 0.f };
            if (k < kn) {
                const float4* p = reinterpret_cast<const float4*>(W + (k0 + k) * 64 + c * 8);
                float4 v0 = p[0], v1 = p[1];
                y[0] = v0.x; y[1] = v0.y; y[2] = v0.z; y[3] = v0.w;
                y[4] = v1.x; y[5] = v1.y; y[6] = v1.z; y[7] = v1.w;
            }
            WU[(k << 3) + (c ^ (k & 7))] = pack8(y);
        }
        #pragma unroll
        for (int j = 0; j < 4; j++) {
            int idx = tid + j * 256;
            int r = idx >> 3, c = idx & 7;
            int rg = tile + r;
            float y[8] = { 0.f, 0.f, 0.f, 0.f, 0.f, 0.f, 0.f, 0.f };
            if (rg < NI) {
                const float* xp = X + rg * F + k0 + c * 8;
                if (c * 8 + 3 < kn) {
                    float4 v = *reinterpret_cast<const float4*>(xp);
                    y[0] = v.x; y[1] = v.y; y[2] = v.z; y[3] = v.w;
                }
                if (c * 8 + 7 < kn) {
                    float4 v = *reinterpret_cast<const float4*>(xp + 4);
                    y[4] = v.x; y[5] = v.y; y[6] = v.z; y[7] = v.w;
                }
            }
            XU[(r << 3) + (c ^ (r & 7))] = pack8(y);
        }
        __syncthreads();
        mma_pass(C, Xh, Wh, tid);
    }

    float yv[4][8];
    epilogue(C, Cs, tid, [&](int i, int r, float* y) {
        int rg = tile + r;
        #pragma unroll
        for (int t = 0; t < 8; t++) y[t] += bias[tx * 8 + t];
        if (rg < NI) g_xih[rg * 8 + tx] = pack8(y);
        #pragma unroll
        for (int t = 0; t < 8; t++) yv[i][t] = y[t];
    });

    // tail: xiT1 = xi_tile @ Wl1_iu
    #pragma unroll
    for (int i = 0; i < 4; i++) {
        int r = ty + 32 * i;
        XU[(r << 3) + (tx ^ (r & 7))] = pack8(yv[i]);
    }
    load_w(Wl, Wh, tid);
    __syncthreads();
    float C2[8][4];
    #pragma unroll
    for (int f = 0; f < 8; f++)
        #pragma unroll
        for (int q = 0; q < 4; q++) C2[f][q] = 0.f;
    mma_pass(C2, Xh, Wh, tid);
    epilogue(C2, Cs, tid, [&](int i, int r, float* y) {
        int rg = tile + r;
        if (rg < NI) g_xiTh[rg * 8 + tx] = pack8(y);
    });
}

// ============================================================================
// fused node update
// ============================================================================
__device__ __forceinline__ void item_tile(
    int tile, const uint4* __restrict__ srcH, const float* __restrict__ Wl,
    const uint4* __restrict__ Xsrc, const float* __restrict__ Wr,
    const float* __restrict__ bias, int relu,
    uint4* __restrict__ Yh, float* __restrict__ Yf,
    const float* __restrict__ WlNext, uint4* __restrict__ xiToutH,
    __half* Xh, __half* Wh, float* Cs)
{
    const int tid = threadIdx.x;
    const int tx = tid & 7, ty = tid >> 3;
    uint4* XU = reinterpret_cast<uint4*>(Xh);

    // gather-mean -> Xh (fp16)
    #pragma unroll 1
    for (int i = 0; i < 4; i++) {
        int r = ty + 32 * i, rg = tile + r;
        float a[8] = { 0.f, 0.f, 0.f, 0.f, 0.f, 0.f, 0.f, 0.f };
        if (rg < NI) gather_mean_h(srcH, g_csrI, g_offI[rg], g_offI[rg + 1], tx, a);
        XU[(r << 3) + (tx ^ (r & 7))] = pack8(a);
    }
    load_w(Wl, Wh, tid);
    __syncthreads();

    float C[8][4];
    #pragma unroll
    for (int f = 0; f < 8; f++)
        #pragma unroll
        for (int q = 0; q < 4; q++) C[f][q] = 0.f;
    mma_pass(C, Xh, Wh, tid);
    __syncthreads();

    load_xh(Xsrc, Xh, tile, NI, tid);
    load_w(Wr, Wh, tid);
    __syncthreads();
    mma_pass(C, Xh, Wh, tid);

    float yv[4][8];
    epilogue(C, Cs, tid, [&](int i, int r, float* y) {
        int rg = tile + r;
        #pragma unroll
        for (int t = 0; t < 8; t++) {
            y[t] += bias[tx * 8 + t];
            if (relu) y[t] = fmaxf(y[t], 0.f);
        }
        if (rg < NI) {
            if (Yh) Yh[rg * 8 + tx] = pack8(y);
            if (Yf) {
                float4* yp = reinterpret_cast<float4*>(Yf + rg * 64 + tx * 8);
                yp[0] = make_float4(y[0], y[1], y[2], y[3]);
                yp[1] = make_float4(y[4], y[5], y[6], y[7]);
            }
        }
        if (WlNext) {
            #pragma unroll
            for (int t = 0; t < 8; t++) yv[i][t] = y[t];
        }
    });

    if (WlNext) {
        #pragma unroll
        for (int i = 0; i < 4; i++) {
            int r = ty + 32 * i;
            XU[(r << 3) + (tx ^ (r & 7))] = pack8(yv[i]);
        }
        load_w(WlNext, Wh, tid);
        __syncthreads();
        float C2[8][4];
        #pragma unroll
        for (int f = 0; f < 8; f++)
            #pragma unroll
            for (int q = 0; q < 4; q++) C2[f][q] = 0.f;
        mma_pass(C2, Xh, Wh, tid);
        epilogue(C2, Cs, tid, [&](int i, int r, float* y) {
            int rg = tile + r;
            if (rg < NI) xiToutH[rg * 8 + tx] = pack8(y);
        });
    }
}

__device__ __forceinline__ void user_tile(
    int tile, const uint4* __restrict__ gsrcH, const uint4* __restrict__ Xsrc,
    const float* __restrict__ Wr, const float* __restrict__ bias, int relu,
    float* __restrict__ Yf, uint4* __restrict__ Yh,
    __half* Xh, __half* Wh, float* Cs)
{
    const int tid = threadIdx.x;
    const int tx = tid & 7, ty = tid >> 3;

    load_xh(Xsrc, Xh, tile, NU, tid);
    load_w(Wr, Wh, tid);
    __syncthreads();

    float C[8][4];
    #pragma unroll
    for (int f = 0; f < 8; f++)
        #pragma unroll
        for (int q = 0; q < 4; q++) C[f][q] = 0.f;
    mma_pass(C, Xh, Wh, tid);

    // gather executed inside the epilogue (short register live-range)
    epilogue(C, Cs, tid, [&](int i, int r, float* y) {
        int rg = tile + r;
        float a[8] = { 0.f, 0.f, 0.f, 0.f, 0.f, 0.f, 0.f, 0.f };
        if (rg < NU) gather_mean_h(gsrcH, g_csrU, g_offU[rg], g_offU[rg + 1], tx, a);
        #pragma unroll
        for (int t = 0; t < 8; t++) {
            y[t] += bias[tx * 8 + t] + a[t];
            if (relu) y[t] = fmaxf(y[t], 0.f);
        }
        if (rg < NU) {
            if (Yh) Yh[rg * 8 + tx] = pack8(y);
            if (Yf) {
                float4* yp = reinterpret_cast<float4*>(Yf + rg * 64 + tx * 8);
                yp[0] = make_float4(y[0], y[1], y[2], y[3]);
                yp[1] = make_float4(y[4], y[5], y[6], y[7]);
            }
        }
    });
}

__global__ __launch_bounds__(256, 3) void k_upd(
    const uint4* __restrict__ itemGsrcH, const float* __restrict__ Wl_ui,
    const uint4* __restrict__ itemXsrc, const float* __restrict__ Wr_ui,
    const float* __restrict__ b_ui, uint4* __restrict__ YiH, float* __restrict__ YiF,
    const uint4* __restrict__ userGsrcH, const uint4* __restrict__ userXsrc,
    const float* __restrict__ Wr_iu, const float* __restrict__ b_iu,
    float* __restrict__ YuF, uint4* __restrict__ YuH,
    const float* __restrict__ WlNext, uint4* __restrict__ xiToutH,
    int relu)
{
    __shared__ __align__(16) __half Xh[128 * 64];
    __shared__ __align__(16) __half Wh[64 * 64];
    __shared__ float Cs[64 * 68];
    if (blockIdx.x < TILES_I) {
        item_tile(blockIdx.x * 128, itemGsrcH, Wl_ui, itemXsrc, Wr_ui, b_ui, relu,
                  YiH, YiF, WlNext, xiToutH, Xh, Wh, Cs);
    } else {
        user_tile((int)(blockIdx.x - TILES_I) * 128, userGsrcH, userXsrc,
                  Wr_iu, b_iu, relu, YuF, YuH, Xh, Wh, Cs);
    }
}

// ---------------- predictor ----------------
__global__ void k_dot(const float* __restrict__ hu, const float* __restrict__ hi,
                      const int* __restrict__ ls, const int* __restrict__ ld,
                      float* __restrict__ out) {
    int i = blockIdx.x * blockDim.x + threadIdx.x;
    int e = i >> 2;
    int j = i & 3;
    if (e >= EL) return;
    int u = ls[e];
    int v = ld[e];
    const float4* pa = reinterpret_cast<const float4*>(hu + u * 64 + j * 16);
    const float4* pb = reinterpret_cast<const float4*>(hi + v * 64 + j * 16);
    float4 a0 = pa[0], a1 = pa[1], a2 = pa[2], a3 = pa[3];
    float4 b0 = pb[0], b1 = pb[1], b2 = pb[2], b3 = pb[3];
    float s = a0.x * b0.x + a0.y * b0.y + a0.z * b0.z + a0.w * b0.w
            + a1.x * b1.x + a1.y * b1.y + a1.z * b1.z + a1.w * b1.w
            + a2.x * b2.x + a2.y * b2.y + a2.z * b2.z + a2.w * b2.w
            + a3.x * b3.x + a3.y * b3.y + a3.z * b3.z + a3.w * b3.w;
    s += __shfl_down_sync(0xffffffffu, s, 2, 4);
    s += __shfl_down_sync(0xffffffffu, s, 1, 4);
    if (j == 0) out[e] = s;
}

// ---------------- launch ----------------
extern "C" void kernel_launch(void* const* d_in, const int* in_sizes, int n_in,
                              void* d_out, int out_size) {
    const float* user_emb = (const float*)d_in[0];
    const float* item_x   = (const float*)d_in[1];
    const float* Wlin     = (const float*)d_in[2];
    const float* blin     = (const float*)d_in[3];
    const float* Wl1_ui   = (const float*)d_in[4];
    const float* Wr1_ui   = (const float*)d_in[5];
    const float* b1_ui    = (const float*)d_in[6];
    const float* Wl1_iu   = (const float*)d_in[7];
    const float* Wr1_iu   = (const float*)d_in[8];
    const float* b1_iu    = (const float*)d_in[9];
    const float* Wl2_ui   = (const float*)d_in[10];
    const float* Wr2_ui   = (const float*)d_in[11];
    const float* b2_ui    = (const float*)d_in[12];
    const float* Wl2_iu   = (const float*)d_in[13];
    const float* Wr2_iu   = (const float*)d_in[14];
    const float* b2_iu    = (const float*)d_in[15];
    const int* es   = (const int*)d_in[17];
    const int* ed   = (const int*)d_in[18];
    const int* ls   = (const int*)d_in[19];
    const int* ldst = (const int*)d_in[20];
    float* out = (float*)d_out;

    uint4 *xih, *hih, *uembh, *huh, *xiTh, *xiT2h;
    float *hu2, *hi2;
    cudaGetSymbolAddress((void**)&xih,   g_xih);
    cudaGetSymbolAddress((void**)&hih,   g_hih);
    cudaGetSymbolAddress((void**)&uembh, g_uembh);
    cudaGetSymbolAddress((void**)&huh,   g_huh);
    cudaGetSymbolAddress((void**)&xiTh,  g_xiTh);
    cudaGetSymbolAddress((void**)&xiT2h, g_xiT2h);
    cudaGetSymbolAddress((void**)&hu2,   g_hu2);
    cudaGetSymbolAddress((void**)&hi2,   g_hi2);

    // 0: zero degrees / cursors / scan state
    k_zero_deg<<<(NU + 255) / 256, 256>>>();
    // 1: fused [item linear (MMA) + fp16 xiT1 || degree count || user_emb fp16 conv]
    k_lin_count<<<TILES_I + EBLK + CONVB, 256>>>(item_x, Wlin, blin, Wl1_iu,
                                                 user_emb, es, ed);
    // 2: fused [exclusive scan || CSR fill]
    k_scanfill<<<NB_I + NB_U + EBLK, 256>>>(es, ed);
    // 3: layer 1 fused [item update (+xiT2 tail) || user update]
    k_upd<<<TILES_I + TILES_U, 256>>>(uembh, Wl1_ui, xih, Wr1_ui, b1_ui, hih, nullptr,
                                      xiTh, uembh, Wr1_iu, b1_iu, nullptr, huh,
                                      Wl2_iu, xiT2h, 1);
    // 4: layer 2 fused (fp32 outputs for the dot)
    k_upd<<<TILES_I + TILES_U, 256>>>(huh, Wl2_ui, hih, Wr2_ui, b2_ui, nullptr, hi2,
                                      xiT2h, huh, Wr2_iu, b2_iu, hu2, nullptr,
                                      nullptr, nullptr, 0);
    // 5: predictor
    k_dot<<<(EL * 4 + 255) / 256, 256>>>(hu2, hi2, ls, ldst, out);
}

// round 16
// speedup vs baseline: 1.4123x; 1.0504x over previous
#include <cuda_runtime.h>
#include <cuda_fp16.h>
#include <cstdint>

static constexpr int NU = 500000;
static constexpr int NI = 100000;
static constexpr int F  = 300;
static constexpr int D  = 64;
static constexpr int E  = 2000000;
static constexpr int EL = 1000000;

static constexpr int TILES_I = (NI + 127) / 128;   // 782
static constexpr int TILES_U = (NU + 127) / 128;   // 3907
static constexpr int EBLK    = (E + 255) / 256;    // 7813
static constexpr int CONVB   = (NU * 8 + 255) / 256;
static constexpr int NB_I    = (NI + 2047) / 2048; // 49
static constexpr int NB_U    = (NU + 2047) / 2048; // 245

// shared buffer: Xh[16KB] + Wh[8KB]; Cs(17.4KB) aliases the same storage
// (Cs is live only inside the epilogue, where Xh/Wh are dead).
static constexpr int SMEM_BYTES = 128 * 64 * 2 + 64 * 64 * 2;   // 24576

// ---------------- device scratch ----------------
__device__ uint4 g_xih  [NI * 8];   // fp16 xi
__device__ uint4 g_hih  [NI * 8];   // fp16 hi (layer-1 item out)
__device__ uint4 g_uembh[NU * 8];   // fp16 user_emb
__device__ uint4 g_huh  [NU * 8];   // fp16 hu (layer-1 user out)
__device__ uint4 g_xiTh [NI * 8];   // fp16 xi @ Wl1_iu
__device__ uint4 g_xiT2h[NI * 8];   // fp16 hi @ Wl2_iu
__device__ float g_hi2[NI * 64];    // fp32 final item (dot)
__device__ float g_hu2[NU * 64];    // fp32 final user (dot)
__device__ int   g_degI[NI];
__device__ int   g_degU[NU];
__device__ int   g_offI[NI + 1];
__device__ int   g_offU[NU + 1];
__device__ int   g_curI[NI];
__device__ int   g_curU[NU];
__device__ int   g_csrI[E];
__device__ int   g_csrU[E];
__device__ volatile int g_sflag[2][256];
__device__ volatile int g_spart[2][256];
__device__ volatile int g_spref[2][256];
__device__ int   g_scan_cnt;

// ---------------- helpers ----------------
__device__ __forceinline__ uint4 pack8(const float* y) {
    uint4 v;
    *reinterpret_cast<__half2*>(&v.x) = __floats2half2_rn(y[0], y[1]);
    *reinterpret_cast<__half2*>(&v.y) = __floats2half2_rn(y[2], y[3]);
    *reinterpret_cast<__half2*>(&v.z) = __floats2half2_rn(y[4], y[5]);
    *reinterpret_cast<__half2*>(&v.w) = __floats2half2_rn(y[6], y[7]);
    return v;
}
__device__ __forceinline__ void acc8(uint4 v, float* s) {
    float2 f0 = __half22float2(*reinterpret_cast<__half2*>(&v.x));
    float2 f1 = __half22float2(*reinterpret_cast<__half2*>(&v.y));
    float2 f2 = __half22float2(*reinterpret_cast<__half2*>(&v.z));
    float2 f3 = __half22float2(*reinterpret_cast<__half2*>(&v.w));
    s[0] += f0.x; s[1] += f0.y; s[2] += f1.x; s[3] += f1.y;
    s[4] += f2.x; s[5] += f2.y; s[6] += f3.x; s[7] += f3.y;
}

__device__ __forceinline__ void ldsm4(unsigned* r, unsigned a) {
    asm volatile("ldmatrix.sync.aligned.m8n8.x4.shared.b16 {%0,%1,%2,%3}, [%4];"
                 : "=r"(r[0]), "=r"(r[1]), "=r"(r[2]), "=r"(r[3]) : "r"(a));
}
__device__ __forceinline__ void ldsm4t(unsigned* r, unsigned a) {
    asm volatile("ldmatrix.sync.aligned.m8n8.x4.trans.shared.b16 {%0,%1,%2,%3}, [%4];"
                 : "=r"(r[0]), "=r"(r[1]), "=r"(r[2]), "=r"(r[3]) : "r"(a));
}
__device__ __forceinline__ void mma16816(float* c, const unsigned* a,
                                         unsigned b0, unsigned b1) {
    asm volatile("mma.sync.aligned.m16n8k16.row.col.f32.f16.f16.f32 "
                 "{%0,%1,%2,%3}, {%4,%5,%6,%7}, {%8,%9}, {%0,%1,%2,%3};"
                 : "+f"(c[0]), "+f"(c[1]), "+f"(c[2]), "+f"(c[3])
                 : "r"(a[0]), "r"(a[1]), "r"(a[2]), "r"(a[3]), "r"(b0), "r"(b1));
}

// C[8][4] += Xh[128x64] @ Wh[64x64]
__device__ __forceinline__ void mma_pass(float (*C)[4], const __half* Xh,
                                         const __half* Wh, int tid) {
    const int lane = tid & 31, wid = tid >> 5;
    const int lm = lane >> 3, lr8 = lane & 7, lmHi = lm >> 1;
    const int rA = wid * 16 + ((lm & 1) << 3) + lr8;
    const int rA7 = rA & 7;
    const int kBoff = ((lm & 1) << 3) + lr8;
    const unsigned xb = (unsigned)__cvta_generic_to_shared(Xh);
    const unsigned wb = (unsigned)__cvta_generic_to_shared(Wh);
    #pragma unroll
    for (int ks = 0; ks < 4; ks++) {
        unsigned a[4];
        int kc = ks * 2 + lmHi;
        ldsm4(a, xb + (unsigned)(((rA << 6) + ((kc ^ rA7) << 3)) * 2));
        int kB = ks * 16 + kBoff;
        int kB7 = kB & 7;
        #pragma unroll
        for (int g = 0; g < 4; g++) {
            unsigned b[4];
            int nc = g * 2 + lmHi;
            ldsm4t(b, wb + (unsigned)(((kB << 6) + ((nc ^ kB7) << 3)) * 2));
            mma16816(C[2 * g],     a, b[0], b[1]);
            mma16816(C[2 * g + 1], a, b[2], b[3]);
        }
    }
}

// W[64x64] fp32 -> Wh swizzled fp16
__device__ __forceinline__ void load_w(const float* W, __half* Wh, int tid) {
    uint4* WU = reinterpret_cast<uint4*>(Wh);
    #pragma unroll
    for (int j = 0; j < 2; j++) {
        int idx = tid + j * 256;
        int k = idx >> 3, c = idx & 7;
        const float4* p = reinterpret_cast<const float4*>(W + k * 64 + c * 8);
        float4 v0 = p[0], v1 = p[1];
        float y[8] = { v0.x, v0.y, v0.z, v0.w, v1.x, v1.y, v1.z, v1.w };
        WU[(k << 3) + (c ^ (k & 7))] = pack8(y);
    }
}
// fp16 global rows -> Xh swizzled
__device__ __forceinline__ void load_xh(const uint4* src, __half* Xh, int tile,
                                        int N, int tid) {
    uint4* XU = reinterpret_cast<uint4*>(Xh);
    #pragma unroll
    for (int j = 0; j < 4; j++) {
        int idx = tid + j * 256;
        int r = idx >> 3, c = idx & 7;
        int rg = tile + r;
        uint4 v = make_uint4(0u, 0u, 0u, 0u);
        if (rg < N) v = src[(rg << 3) + c];
        XU[(r << 3) + (c ^ (r & 7))] = v;
    }
}

// epilogue: C frags -> Cs (two halves) -> fn(i, r, y[8]) in (ty,tx) mapping.
// Cs may alias Xh/Wh: all reads of Xh/Wh complete before the first barrier,
// and callers only re-stage Xh after this returns (closing barrier).
template <typename Fn>
__device__ __forceinline__ void epilogue(float (*C)[4], float* Cs, int tid, Fn fn) {
    const int lane = tid & 31, wid = tid >> 5;
    const int tx = tid & 7, ty = tid >> 3;
    #pragma unroll
    for (int h = 0; h < 2; h++) {
        __syncthreads();
        if ((wid >> 2) == h) {
            int lr = ((wid & 3) << 4) + (lane >> 2);
            int col = (lane & 3) * 2;
            #pragma unroll
            for (int f = 0; f < 8; f++) {
                *reinterpret_cast<float2*>(&Cs[lr * 68 + f * 8 + col]) =
                    make_float2(C[f][0], C[f][1]);
                *reinterpret_cast<float2*>(&Cs[(lr + 8) * 68 + f * 8 + col]) =
                    make_float2(C[f][2], C[f][3]);
            }
        }
        __syncthreads();
        #pragma unroll
        for (int ii = 0; ii < 2; ii++) {
            int i = 2 * h + ii;
            int r = ty + 32 * i;
            int lr = r - 64 * h;
            float4 v0 = *reinterpret_cast<const float4*>(&Cs[lr * 68 + tx * 8]);
            float4 v1 = *reinterpret_cast<const float4*>(&Cs[lr * 68 + tx * 8 + 4]);
            float y[8] = { v0.x, v0.y, v0.z, v0.w, v1.x, v1.y, v1.z, v1.w };
            fn(i, r, y);
        }
    }
    __syncthreads();
}

// ---------------- 4-edge unrolled fp16 gather-mean ----------------
__device__ __forceinline__ void gather_mean_h(
    const uint4* __restrict__ feat, const int* __restrict__ csr,
    int p0, int p1, int tx, float* a)
{
    float s[8];
    #pragma unroll
    for (int t = 0; t < 8; t++) s[t] = 0.f;
    int p = p0;
    for (; p + 4 <= p1; p += 4) {
        int i0 = csr[p], i1 = csr[p + 1], i2 = csr[p + 2], i3 = csr[p + 3];
        uint4 v0 = feat[i0 * 8 + tx];
        uint4 v1 = feat[i1 * 8 + tx];
        uint4 v2 = feat[i2 * 8 + tx];
        uint4 v3 = feat[i3 * 8 + tx];
        acc8(v0, s); acc8(v1, s); acc8(v2, s); acc8(v3, s);
    }
    for (; p < p1; p++) acc8(feat[csr[p] * 8 + tx], s);
    float rc = 1.f / fmaxf((float)(p1 - p0), 1.f);
    #pragma unroll
    for (int t = 0; t < 8; t++) a[t] += rc * s[t];
}

// ---------------- zero ----------------
__global__ void k_zero_deg() {
    int i = blockIdx.x * blockDim.x + threadIdx.x;
    if (i < NU) { g_degU[i] = 0; g_curU[i] = 0; }
    if (i < NI) { g_degI[i] = 0; g_curI[i] = 0; }
    if (i < 256) { g_sflag[0][i] = 0; g_sflag[1][i] = 0; }
    if (i == 0) g_scan_cnt = 0;
}

// ---------------- fused scan (decoupled lookback) + CSR fill ----------------
__global__ void k_scanfill(const int* __restrict__ es, const int* __restrict__ ed) {
    const int t = threadIdx.x;
    if (blockIdx.x >= NB_I + NB_U) {
        if (t == 0) {
            volatile int* cnt = &g_scan_cnt;
            while (*cnt < NB_I + NB_U) { }
        }
        __syncthreads();
        int e = (int)(blockIdx.x - NB_I - NB_U) * 256 + t;
        if (e < E) {
            int u = es[e], it = ed[e];
            g_csrI[g_offI[it] + atomicAdd(&g_curI[it], 1)] = u;
            g_csrU[g_offU[u] + atomicAdd(&g_curU[u], 1)] = it;
        }
        return;
    }

    int dom, blk, n;
    const int* deg; int* out;
    if (blockIdx.x < NB_I) { dom = 0; blk = blockIdx.x;        deg = g_degI; out = g_offI; n = NI; }
    else                   { dom = 1; blk = blockIdx.x - NB_I; deg = g_degU; out = g_offU; n = NU; }

    __shared__ int ws[8];
    __shared__ int s_tot;
    __shared__ int s_exc;
    const int base = blk * 2048 + t * 8;
    int v[8];
    #pragma unroll
    for (int j = 0; j < 8; j++) v[j] = (base + j < n) ? deg[base + j] : 0;
    int s = 0;
    #pragma unroll
    for (int j = 0; j < 8; j++) { int x = v[j]; v[j] = s; s += x; }
    const int lane = t & 31, wid = t >> 5;
    int sx = s;
    #pragma unroll
    for (int o = 1; o < 32; o <<= 1) {
        int y = __shfl_up_sync(0xffffffffu, sx, o);
        if (lane >= o) sx += y;
    }
    if (lane == 31) ws[wid] = sx;
    __syncthreads();
    if (wid == 0 && lane < 8) {
        int b = ws[lane];
        int bx = b;
        #pragma unroll
        for (int o = 1; o < 8; o <<= 1) {
            int y = __shfl_up_sync(0xffu, bx, o);
            if (lane >= o) bx += y;
        }
        ws[lane] = bx - b;
        if (lane == 7) s_tot = bx;
    }
    __syncthreads();
    const int loff = ws[wid] + (sx - s);

    if (t == 0) {
        int tot = s_tot;
        g_spart[dom][blk] = tot;
        __threadfence();
        if (blk == 0) {
            g_spref[dom][0] = tot;
            __threadfence();
            g_sflag[dom][0] = 2;
            s_exc = 0;
        } else {
            g_sflag[dom][blk] = 1;
            int exc = 0;
            int pb = blk - 1;
            while (pb >= 0) {
                int f;
                while ((f = g_sflag[dom][pb]) == 0) { }
                if (f == 2) { exc += g_spref[dom][pb]; break; }
                exc += g_spart[dom][pb];
                pb--;
            }
            g_spref[dom][blk] = exc + tot;
            __threadfence();
            g_sflag[dom][blk] = 2;
            s_exc = exc;
        }
    }
    __syncthreads();
    const int exc = s_exc;
    #pragma unroll
    for (int j = 0; j < 8; j++)
        if (base + j < n) out[base + j] = exc + loff + v[j];
    if (blockIdx.x == 0 && t == 0) { g_offI[NI] = E; g_offU[NU] = E; }

    __syncthreads();
    if (t == 0) {
        __threadfence();
        atomicAdd(&g_scan_cnt, 1);
    }
}

// ============================================================================
// fused: [item linear (MMA) + fp16 xiT1 tail] || degree count || user_emb conv
// ============================================================================
__global__ __launch_bounds__(256, 3) void k_lin_count(
    const float* __restrict__ X, const float* __restrict__ W,
    const float* __restrict__ bias, const float* __restrict__ Wl,
    const float* __restrict__ ue,
    const int* __restrict__ es, const int* __restrict__ ed)
{
    if (blockIdx.x >= TILES_I + EBLK) {
        int i = (int)(blockIdx.x - TILES_I - EBLK) * 256 + threadIdx.x;
        if (i < NU * 8) {
            int row = i >> 3, part = i & 7;
            const float4* p = reinterpret_cast<const float4*>(ue + row * 64 + part * 8);
            float4 v0 = p[0], v1 = p[1];
            float y[8] = { v0.x, v0.y, v0.z, v0.w, v1.x, v1.y, v1.z, v1.w };
            g_uembh[i] = pack8(y);
        }
        return;
    }
    if (blockIdx.x >= TILES_I) {
        int i = (int)(blockIdx.x - TILES_I) * 256 + threadIdx.x;
        if (i < E) {
            atomicAdd(&g_degU[es[i]], 1);
            atomicAdd(&g_degI[ed[i]], 1);
        }
        return;
    }

    __shared__ __align__(16) unsigned char sbuf[SMEM_BYTES];
    __half* Xh = reinterpret_cast<__half*>(sbuf);
    __half* Wh = reinterpret_cast<__half*>(sbuf + 128 * 64 * 2);
    float*  Cs = reinterpret_cast<float*>(sbuf);          // aliases Xh/Wh
    const int tid = threadIdx.x;
    const int tx = tid & 7, ty = tid >> 3;
    const int tile = blockIdx.x * 128;
    uint4* XU = reinterpret_cast<uint4*>(Xh);
    uint4* WU = reinterpret_cast<uint4*>(Wh);

    float C[8][4];
    #pragma unroll
    for (int f = 0; f < 8; f++)
        #pragma unroll
        for (int q = 0; q < 4; q++) C[f][q] = 0.f;

    #pragma unroll 1
    for (int kc = 0; kc < 5; kc++) {
        const int k0 = kc * 64;
        const int kn = (k0 + 64 <= F) ? 64 : (F - k0);
        __syncthreads();
        #pragma unroll
        for (int j = 0; j < 2; j++) {
            int idx = tid + j * 256;
            int k = idx >> 3, c = idx & 7;
            float y[8] = { 0.f, 0.f, 0.f, 0.f, 0.f, 0.f, 0.f, 0.f };
            if (k < kn) {
                const float4* p = reinterpret_cast<const float4*>(W + (k0 + k) * 64 + c * 8);
                float4 v0 = p[0], v1 = p[1];
                y[0] = v0.x; y[1] = v0.y; y[2] = v0.z; y[3] = v0.w;
                y[4] = v1.x; y[5] = v1.y; y[6] = v1.z; y[7] = v1.w;
            }
            WU[(k << 3) + (c ^ (k & 7))] = pack8(y);
        }
        #pragma unroll
        for (int j = 0; j < 4; j++) {
            int idx = tid + j * 256;
            int r = idx >> 3, c = idx & 7;
            int rg = tile + r;
            float y[8] = { 0.f, 0.f, 0.f, 0.f, 0.f, 0.f, 0.f, 0.f };
            if (rg < NI) {
                const float* xp = X + rg * F + k0 + c * 8;
                if (c * 8 + 3 < kn) {
                    float4 v = *reinterpret_cast<const float4*>(xp);
                    y[0] = v.x; y[1] = v.y; y[2] = v.z; y[3] = v.w;
                }
                if (c * 8 + 7 < kn) {
                    float4 v = *reinterpret_cast<const float4*>(xp + 4);
                    y[4] = v.x; y[5] = v.y; y[6] = v.z; y[7] = v.w;
                }
            }
            XU[(r << 3) + (c ^ (r & 7))] = pack8(y);
        }
        __syncthreads();
        mma_pass(C, Xh, Wh, tid);
    }

    float yv[4][8];
    epilogue(C, Cs, tid, [&](int i, int r, float* y) {
        int rg = tile + r;
        #pragma unroll
        for (int t = 0; t < 8; t++) y[t] += bias[tx * 8 + t];
        if (rg < NI) g_xih[rg * 8 + tx] = pack8(y);
        #pragma unroll
        for (int t = 0; t < 8; t++) yv[i][t] = y[t];
    });

    // tail: xiT1 = xi_tile @ Wl1_iu
    #pragma unroll
    for (int i = 0; i < 4; i++) {
        int r = ty + 32 * i;
        XU[(r << 3) + (tx ^ (r & 7))] = pack8(yv[i]);
    }
    load_w(Wl, Wh, tid);
    __syncthreads();
    float C2[8][4];
    #pragma unroll
    for (int f = 0; f < 8; f++)
        #pragma unroll
        for (int q = 0; q < 4; q++) C2[f][q] = 0.f;
    mma_pass(C2, Xh, Wh, tid);
    epilogue(C2, Cs, tid, [&](int i, int r, float* y) {
        int rg = tile + r;
        if (rg < NI) g_xiTh[rg * 8 + tx] = pack8(y);
    });
}

// ============================================================================
// fused node update
// ============================================================================
__device__ __forceinline__ void item_tile(
    int tile, const uint4* __restrict__ srcH, const float* __restrict__ Wl,
    const uint4* __restrict__ Xsrc, const float* __restrict__ Wr,
    const float* __restrict__ bias, int relu,
    uint4* __restrict__ Yh, float* __restrict__ Yf,
    const float* __restrict__ WlNext, uint4* __restrict__ xiToutH,
    __half* Xh, __half* Wh, float* Cs)
{
    const int tid = threadIdx.x;
    const int tx = tid & 7, ty = tid >> 3;
    uint4* XU = reinterpret_cast<uint4*>(Xh);

    // gather-mean -> Xh (fp16)
    #pragma unroll 1
    for (int i = 0; i < 4; i++) {
        int r = ty + 32 * i, rg = tile + r;
        float a[8] = { 0.f, 0.f, 0.f, 0.f, 0.f, 0.f, 0.f, 0.f };
        if (rg < NI) gather_mean_h(srcH, g_csrI, g_offI[rg], g_offI[rg + 1], tx, a);
        XU[(r << 3) + (tx ^ (r & 7))] = pack8(a);
    }
    load_w(Wl, Wh, tid);
    __syncthreads();

    float C[8][4];
    #pragma unroll
    for (int f = 0; f < 8; f++)
        #pragma unroll
        for (int q = 0; q < 4; q++) C[f][q] = 0.f;
    mma_pass(C, Xh, Wh, tid);
    __syncthreads();

    load_xh(Xsrc, Xh, tile, NI, tid);
    load_w(Wr, Wh, tid);
    __syncthreads();
    mma_pass(C, Xh, Wh, tid);

    float yv[4][8];
    epilogue(C, Cs, tid, [&](int i, int r, float* y) {
        int rg = tile + r;
        #pragma unroll
        for (int t = 0; t < 8; t++) {
            y[t] += bias[tx * 8 + t];
            if (relu) y[t] = fmaxf(y[t], 0.f);
        }
        if (rg < NI) {
            if (Yh) Yh[rg * 8 + tx] = pack8(y);
            if (Yf) {
                float4* yp = reinterpret_cast<float4*>(Yf + rg * 64 + tx * 8);
                yp[0] = make_float4(y[0], y[1], y[2], y[3]);
                yp[1] = make_float4(y[4], y[5], y[6], y[7]);
            }
        }
        if (WlNext) {
            #pragma unroll
            for (int t = 0; t < 8; t++) yv[i][t] = y[t];
        }
    });

    if (WlNext) {
        #pragma unroll
        for (int i = 0; i < 4; i++) {
            int r = ty + 32 * i;
            XU[(r << 3) + (tx ^ (r & 7))] = pack8(yv[i]);
        }
        load_w(WlNext, Wh, tid);
        __syncthreads();
        float C2[8][4];
        #pragma unroll
        for (int f = 0; f < 8; f++)
            #pragma unroll
            for (int q = 0; q < 4; q++) C2[f][q] = 0.f;
        mma_pass(C2, Xh, Wh, tid);
        epilogue(C2, Cs, tid, [&](int i, int r, float* y) {
            int rg = tile + r;
            if (rg < NI) xiToutH[rg * 8 + tx] = pack8(y);
        });
    }
}

__device__ __forceinline__ void user_tile(
    int tile, const uint4* __restrict__ gsrcH, const uint4* __restrict__ Xsrc,
    const float* __restrict__ Wr, const float* __restrict__ bias, int relu,
    float* __restrict__ Yf, uint4* __restrict__ Yh,
    __half* Xh, __half* Wh, float* Cs)
{
    const int tid = threadIdx.x;
    const int tx = tid & 7;

    load_xh(Xsrc, Xh, tile, NU, tid);
    load_w(Wr, Wh, tid);
    __syncthreads();

    float C[8][4];
    #pragma unroll
    for (int f = 0; f < 8; f++)
        #pragma unroll
        for (int q = 0; q < 4; q++) C[f][q] = 0.f;
    mma_pass(C, Xh, Wh, tid);

    // gather executed inside the epilogue (short register live-range)
    epilogue(C, Cs, tid, [&](int i, int r, float* y) {
        int rg = tile + r;
        float a[8] = { 0.f, 0.f, 0.f, 0.f, 0.f, 0.f, 0.f, 0.f };
        if (rg < NU) gather_mean_h(gsrcH, g_csrU, g_offU[rg], g_offU[rg + 1], tx, a);
        #pragma unroll
        for (int t = 0; t < 8; t++) {
            y[t] += bias[tx * 8 + t] + a[t];
            if (relu) y[t] = fmaxf(y[t], 0.f);
        }
        if (rg < NU) {
            if (Yh) Yh[rg * 8 + tx] = pack8(y);
            if (Yf) {
                float4* yp = reinterpret_cast<float4*>(Yf + rg * 64 + tx * 8);
                yp[0] = make_float4(y[0], y[1], y[2], y[3]);
                yp[1] = make_float4(y[4], y[5], y[6], y[7]);
            }
        }
    });
}

__global__ __launch_bounds__(256, 4) void k_upd(
    const uint4* __restrict__ itemGsrcH, const float* __restrict__ Wl_ui,
    const uint4* __restrict__ itemXsrc, const float* __restrict__ Wr_ui,
    const float* __restrict__ b_ui, uint4* __restrict__ YiH, float* __restrict__ YiF,
    const uint4* __restrict__ userGsrcH, const uint4* __restrict__ userXsrc,
    const float* __restrict__ Wr_iu, const float* __restrict__ b_iu,
    float* __restrict__ YuF, uint4* __restrict__ YuH,
    const float* __restrict__ WlNext, uint4* __restrict__ xiToutH,
    int relu)
{
    __shared__ __align__(16) unsigned char sbuf[SMEM_BYTES];
    __half* Xh = reinterpret_cast<__half*>(sbuf);
    __half* Wh = reinterpret_cast<__half*>(sbuf + 128 * 64 * 2);
    float*  Cs = reinterpret_cast<float*>(sbuf);          // aliases Xh/Wh
    if (blockIdx.x < TILES_I) {
        item_tile(blockIdx.x * 128, itemGsrcH, Wl_ui, itemXsrc, Wr_ui, b_ui, relu,
                  YiH, YiF, WlNext, xiToutH, Xh, Wh, Cs);
    } else {
        user_tile((int)(blockIdx.x - TILES_I) * 128, userGsrcH, userXsrc,
                  Wr_iu, b_iu, relu, YuF, YuH, Xh, Wh, Cs);
    }
}

// ---------------- predictor ----------------
__global__ void k_dot(const float* __restrict__ hu, const float* __restrict__ hi,
                      const int* __restrict__ ls, const int* __restrict__ ld,
                      float* __restrict__ out) {
    int i = blockIdx.x * blockDim.x + threadIdx.x;
    int e = i >> 2;
    int j = i & 3;
    if (e >= EL) return;
    int u = ls[e];
    int v = ld[e];
    const float4* pa = reinterpret_cast<const float4*>(hu + u * 64 + j * 16);
    const float4* pb = reinterpret_cast<const float4*>(hi + v * 64 + j * 16);
    float4 a0 = pa[0], a1 = pa[1], a2 = pa[2], a3 = pa[3];
    float4 b0 = pb[0], b1 = pb[1], b2 = pb[2], b3 = pb[3];
    float s = a0.x * b0.x + a0.y * b0.y + a0.z * b0.z + a0.w * b0.w
            + a1.x * b1.x + a1.y * b1.y + a1.z * b1.z + a1.w * b1.w
            + a2.x * b2.x + a2.y * b2.y + a2.z * b2.z + a2.w * b2.w
            + a3.x * b3.x + a3.y * b3.y + a3.z * b3.z + a3.w * b3.w;
    s += __shfl_down_sync(0xffffffffu, s, 2, 4);
    s += __shfl_down_sync(0xffffffffu, s, 1, 4);
    if (j == 0) out[e] = s;
}

// ---------------- launch ----------------
extern "C" void kernel_launch(void* const* d_in, const int* in_sizes, int n_in,
                              void* d_out, int out_size) {
    const float* user_emb = (const float*)d_in[0];
    const float* item_x   = (const float*)d_in[1];
    const float* Wlin     = (const float*)d_in[2];
    const float* blin     = (const float*)d_in[3];
    const float* Wl1_ui   = (const float*)d_in[4];
    const float* Wr1_ui   = (const float*)d_in[5];
    const float* b1_ui    = (const float*)d_in[6];
    const float* Wl1_iu   = (const float*)d_in[7];
    const float* Wr1_iu   = (const float*)d_in[8];
    const float* b1_iu    = (const float*)d_in[9];
    const float* Wl2_ui   = (const float*)d_in[10];
    const float* Wr2_ui   = (const float*)d_in[11];
    const float* b2_ui    = (const float*)d_in[12];
    const float* Wl2_iu   = (const float*)d_in[13];
    const float* Wr2_iu   = (const float*)d_in[14];
    const float* b2_iu    = (const float*)d_in[15];
    const int* es   = (const int*)d_in[17];
    const int* ed   = (const int*)d_in[18];
    const int* ls   = (const int*)d_in[19];
    const int* ldst = (const int*)d_in[20];
    float* out = (float*)d_out;

    uint4 *xih, *hih, *uembh, *huh, *xiTh, *xiT2h;
    float *hu2, *hi2;
    cudaGetSymbolAddress((void**)&xih,   g_xih);
    cudaGetSymbolAddress((void**)&hih,   g_hih);
    cudaGetSymbolAddress((void**)&uembh, g_uembh);
    cudaGetSymbolAddress((void**)&huh,   g_huh);
    cudaGetSymbolAddress((void**)&xiTh,  g_xiTh);
    cudaGetSymbolAddress((void**)&xiT2h, g_xiT2h);
    cudaGetSymbolAddress((void**)&hu2,   g_hu2);
    cudaGetSymbolAddress((void**)&hi2,   g_hi2);

    // 0: zero degrees / cursors / scan state
    k_zero_deg<<<(NU + 255) / 256, 256>>>();
    // 1: fused [item linear (MMA) + fp16 xiT1 || degree count || user_emb fp16 conv]
    k_lin_count<<<TILES_I + EBLK + CONVB, 256>>>(item_x, Wlin, blin, Wl1_iu,
                                                 user_emb, es, ed);
    // 2: fused [exclusive scan || CSR fill]
    k_scanfill<<<NB_I + NB_U + EBLK, 256>>>(es, ed);
    // 3: layer 1 fused [item update (+xiT2 tail) || user update]
    k_upd<<<TILES_I + TILES_U, 256>>>(uembh, Wl1_ui, xih, Wr1_ui, b1_ui, hih, nullptr,
                                      xiTh, uembh, Wr1_iu, b1_iu, nullptr, huh,
                                      Wl2_iu, xiT2h, 1);
    // 4: layer 2 fused (fp32 outputs for the dot)
    k_upd<<<TILES_I + TILES_U, 256>>>(huh, Wl2_ui, hih, Wr2_ui, b2_ui, nullptr, hi2,
                                      xiT2h, huh, Wr2_iu, b2_iu, hu2, nullptr,
                                      nullptr, nullptr, 0);
    // 5: predictor
    k_dot<<<(EL * 4 + 255) / 256, 256>>>(hu2, hi2, ls, ldst, out);
}